// round 14
// baseline (speedup 1.0000x reference)
#include <cuda_runtime.h>
#include <cuda_fp16.h>
#include <cstdint>
#include <cstddef>

#define NROWS  8192
#define INF    1024
#define OUTF   1024
#define KDIM   9216
#define KSTEP  32
#define NIT    288          // KDIM / 32
#define STAGES 5
#define PDIST  3            // prefetch distance (slack = STAGES-1-PDIST = 1)
#define ROWB   80           // 64 data bytes + 16 pad (conflict-free, r*5 mod 8)
#define A_SZ   (128 * ROWB)         // 10240
#define B_SZ   (128 * ROWB)         // 10240
#define STAGE_SZ (A_SZ + B_SZ)      // 20480
#define BAR_OFF (STAGES * STAGE_SZ) // 102400
#define SMEM_BYTES (BAR_OFF + 96)   // 102496 (x2 CTAs = 204992 <= 228KB)
#define NTHR   256

// ---------------- scratch (device globals) ----------------------------------
__device__ __align__(1024) __half g_G[(size_t)NROWS * KDIM];
__device__ __align__(1024) __half g_W[(size_t)OUTF * KDIM];

// ---------------- helpers ----------------------------------------------------
static __device__ __forceinline__ uint32_t smem_u32(const void* p) {
    uint32_t a;
    asm("{ .reg .u64 t; cvta.to.shared.u64 t, %1; cvt.u32.u64 %0, t; }"
        : "=r"(a) : "l"(p));
    return a;
}
static __device__ __forceinline__ void cp16(uint32_t s, const void* g) {
    asm volatile("cp.async.cg.shared.global [%0], [%1], 16;" :: "r"(s), "l"(g));
}
static __device__ __forceinline__ void cp_commit() {
    asm volatile("cp.async.commit_group;" ::: "memory");
}
static __device__ __forceinline__ void cp_wait3() {
    asm volatile("cp.async.wait_group 3;" ::: "memory");
}
static __device__ __forceinline__ void mbar_init(uint32_t m, uint32_t c) {
    asm volatile("mbarrier.init.shared.b64 [%0], %1;" :: "r"(m), "r"(c) : "memory");
}
static __device__ __forceinline__ void mbar_arrive(uint32_t m) {
    asm volatile("mbarrier.arrive.shared.b64 _, [%0];" :: "r"(m) : "memory");
}
static __device__ __forceinline__ void mbar_wait(uint32_t m, uint32_t ph) {
    asm volatile(
        "{\n\t.reg .pred P;\n"
        "LW_%=:\n\t"
        "mbarrier.try_wait.parity.shared.b64 P, [%0], %1;\n\t"
        "@P bra LD_%=;\n\t"
        "bra LW_%=;\n"
        "LD_%=:\n\t}"
        :: "r"(m), "r"(ph) : "memory");
}
#define LDSM4(r, adr) \
    asm volatile("ldmatrix.sync.aligned.m8n8.x4.shared.b16 {%0,%1,%2,%3}, [%4];" \
                 : "=r"((r)[0]), "=r"((r)[1]), "=r"((r)[2]), "=r"((r)[3]) \
                 : "r"(adr))
static __device__ __forceinline__ void mma16816(
    float* c, const uint32_t* a, uint32_t b0, uint32_t b1)
{
    asm volatile(
        "mma.sync.aligned.m16n8k16.row.col.f32.f16.f16.f32 "
        "{%0,%1,%2,%3}, {%4,%5,%6,%7}, {%8,%9}, {%0,%1,%2,%3};"
        : "+f"(c[0]), "+f"(c[1]), "+f"(c[2]), "+f"(c[3])
        : "r"(a[0]), "r"(a[1]), "r"(a[2]), "r"(a[3]), "r"(b0), "r"(b1));
}
static __device__ __forceinline__ uint32_t pack_h2(float a, float b) {
    __half2 t = __floats2half2_rn(a, b);
    return *reinterpret_cast<uint32_t*>(&t);
}

// ---------------- kernel 1: prep (W convert + features), merged --------------
__global__ void prep_kernel(const float* __restrict__ spline_w,
                            const float* __restrict__ base_w,
                            const float* __restrict__ x,
                            const float* __restrict__ gamma,
                            const float* __restrict__ beta)
{
    const int tid = threadIdx.x;            // 256 threads

    if (blockIdx.x < OUTF) {
        const int o = blockIdx.x;
        const size_t rb = (size_t)o * KDIM;
        for (int k = tid; k < KDIM; k += 256) {
            float v = (k < 8192) ? spline_w[(size_t)o * 8192 + k]
                                 : base_w[(size_t)o * 1024 + (k - 8192)];
            g_W[rb + k] = __float2half_rn(v);
        }
        return;
    }

    const int row = blockIdx.x - OUTF;
    const int lane = tid & 31, wid = tid >> 5;

    const float4 v = reinterpret_cast<const float4*>(x + (size_t)row * INF)[tid];
    float s  = v.x + v.y + v.z + v.w;
    float sq = v.x * v.x + v.y * v.y + v.z * v.z + v.w * v.w;
#pragma unroll
    for (int o = 16; o > 0; o >>= 1) {
        s  += __shfl_xor_sync(0xFFFFFFFFu, s,  o);
        sq += __shfl_xor_sync(0xFFFFFFFFu, sq, o);
    }
    __shared__ float rs[8], rq[8], s_mu, s_rstd;
    if (lane == 0) { rs[wid] = s; rq[wid] = sq; }
    __syncthreads();
    if (tid == 0) {
        float S = 0.f, Q = 0.f;
#pragma unroll
        for (int i = 0; i < 8; i++) { S += rs[i]; Q += rq[i]; }
        float mu = S * (1.0f / INF);
        float var = Q * (1.0f / INF) - mu * mu;
        s_mu = mu;
        s_rstd = rsqrtf(var + 1e-5f);
    }
    __syncthreads();
    const float mu = s_mu, rstd = s_rstd;

    __half* gh = g_G + (size_t)row * KDIM;
    const float xv4[4] = { v.x, v.y, v.z, v.w };

#pragma unroll
    for (int e = 0; e < 4; e++) {
        const int in = tid * 4 + e;
        const float xv = xv4[e];
        const float xn = (xv - mu) * rstd * gamma[in] + beta[in];
        const float t0 = (xn + 2.0f) * 1.75f;   // (xn - grid_g)/DENOM = t0 - g
        float b[8];
#pragma unroll
        for (int g = 0; g < 8; g++) {
            float d = t0 - (float)g;
            b[g] = __expf(-d * d);
        }
        uint4 H;
        H.x = pack_h2(b[0], b[1]); H.y = pack_h2(b[2], b[3]);
        H.z = pack_h2(b[4], b[5]); H.w = pack_h2(b[6], b[7]);
        *reinterpret_cast<uint4*>(gh + (size_t)in * 8) = H;

        float sl = xv / (1.0f + __expf(-xv));     // silu(x), original x
        gh[8192 + in] = __float2half_rn(sl);
    }
}

// ---------------- kernel 2: mma.sync GEMM  Y = G W^T + b ---------------------
// CTA 128x128, 8 warps of 32x64 (4m x 2n), K-step 32, 5-stage mbarrier ring
// with prefetch distance 3 (drift slack 1 stage), 2 CTAs / SM.
__global__ void __launch_bounds__(NTHR, 2)
gemm_kernel(const float* __restrict__ bias, float* __restrict__ out)
{
    extern __shared__ __align__(128) char smem[];
    const uint32_t sb = smem_u32(smem);
    const int tid  = threadIdx.x;
    const int lane = tid & 31;
    const int wid  = tid >> 5;
    const int warp_m = wid & 3;     // 4 x 32 rows
    const int warp_n = wid >> 2;    // 2 x 64 cols
    const int n0 = blockIdx.x * 128;
    const int m0 = blockIdx.y * 128;

    const uint32_t fullb  = sb + BAR_OFF;        // full[s]  = fullb + 8*s
    const uint32_t emptyb = sb + BAR_OFF + 8u * STAGES;

    if (tid == 0) {
#pragma unroll
        for (int s = 0; s < STAGES; s++) {
            mbar_init(fullb + 8u * s, 8);
            mbar_init(emptyb + 8u * s, 8);
        }
    }
    __syncthreads();    // barrier init visible (outside main loop)

    // ---- cp.async per-thread geometry (16B chunks, 4 per 64B row) ----
    const __half* baseG = g_G;
    const __half* baseW = g_W;
    uint32_t dA[2], gA[2];
#pragma unroll
    for (int j = 0; j < 2; j++) {                 // A: 512 chunks / 256 thr
        int c = tid + NTHR * j;
        int r = c >> 2, sgs = c & 3;
        dA[j] = (uint32_t)(r * ROWB + sgs * 16);
        gA[j] = (uint32_t)((m0 + r) * KDIM + sgs * 8);
    }
    uint32_t dB[2], gB[2];
#pragma unroll
    for (int j = 0; j < 2; j++) {                 // B: 512 chunks / 256 thr
        int c = tid + NTHR * j;
        int r = c >> 2, sgs = c & 3;
        dB[j] = (uint32_t)(A_SZ + r * ROWB + sgs * 16);
        gB[j] = (uint32_t)((n0 + r) * KDIM + sgs * 8);
    }

    auto load_stage = [&](int it, int stg) {
        const uint32_t kcol = (uint32_t)it * KSTEP;
        const uint32_t st = sb + (uint32_t)(stg * STAGE_SZ);
#pragma unroll
        for (int j = 0; j < 2; j++) cp16(st + dA[j], baseG + gA[j] + kcol);
#pragma unroll
        for (int j = 0; j < 2; j++) cp16(st + dB[j], baseW + gB[j] + kcol);
    };

    // ---- ldmatrix per-thread lane offsets ----
    const uint32_t aLane = (uint32_t)((warp_m * 32 + ((lane >> 3) & 1) * 8 + (lane & 7)) * ROWB
                                      + (lane >> 4) * 16);
    const uint32_t bLane = (uint32_t)(A_SZ
                                      + (warp_n * 64 + ((lane >> 4) & 1) * 8 + (lane & 7)) * ROWB
                                      + ((lane >> 3) & 1) * 16);

    float acc[64];
#pragma unroll
    for (int i = 0; i < 64; i++) acc[i] = 0.0f;

    // prologue: fill stages 0..2 (chunks 0..2)
    load_stage(0, 0); cp_commit();
    load_stage(1, 1); cp_commit();
    load_stage(2, 2); cp_commit();

    int sc = 0, pc = 0;     // consumer stage + phase parity
    int sp = PDIST, fp = 0; // producer stage (for chunk it+PDIST) + wrap count

    for (int it = 0; it < NIT; it++) {
        // producer: refill stage sp with chunk it+PDIST
        if (it + PDIST < NIT) {
            if (fp >= 1) mbar_wait(emptyb + 8u * sp, (uint32_t)((fp - 1) & 1));
            load_stage(it + PDIST, sp);
        }
        cp_commit();                       // uniform group count
        cp_wait3();                        // own copies for stage sc complete
        __syncwarp();
        if (lane == 0) mbar_arrive(fullb + 8u * sc);
        mbar_wait(fullb + 8u * sc, (uint32_t)pc);

        const uint32_t st = sb + (uint32_t)(sc * STAGE_SZ);
#pragma unroll
        for (int kh = 0; kh < 2; kh++) {
            const uint32_t khoff = (uint32_t)(kh * 32);
            uint32_t a[2][4], b[4][4];
#pragma unroll
            for (int ms = 0; ms < 2; ms++)
                LDSM4(a[ms], st + aLane + (uint32_t)(ms * 16 * ROWB) + khoff);
#pragma unroll
            for (int p = 0; p < 4; p++)
                LDSM4(b[p], st + bLane + (uint32_t)(p * 16 * ROWB) + khoff);
#pragma unroll
            for (int ms = 0; ms < 2; ms++) {
#pragma unroll
                for (int p = 0; p < 4; p++) {
                    mma16816(acc + (ms * 8 + 2 * p) * 4,     a[ms], b[p][0], b[p][1]);
                    mma16816(acc + (ms * 8 + 2 * p + 1) * 4, a[ms], b[p][2], b[p][3]);
                }
            }
        }
        __syncwarp();
        if (lane == 0) mbar_arrive(emptyb + 8u * sc);

        if (++sc == STAGES) { sc = 0; pc ^= 1; }
        if (++sp == STAGES) { sp = 0; fp++; }
    }

    // ---- epilogue: add bias, store fp32 ----
    const int rbase = m0 + warp_m * 32 + (lane >> 2);
    const int cbase = n0 + warp_n * 64 + (lane & 3) * 2;
#pragma unroll
    for (int ms = 0; ms < 2; ms++) {
#pragma unroll
        for (int ns = 0; ns < 8; ns++) {
            const float* c = acc + (ms * 8 + ns) * 4;
            const int col = cbase + ns * 8;
            const float2 bb = *reinterpret_cast<const float2*>(bias + col);
            const int r0 = rbase + ms * 16;
            float2 o0 = { c[0] + bb.x, c[1] + bb.y };
            float2 o1 = { c[2] + bb.x, c[3] + bb.y };
            *reinterpret_cast<float2*>(out + (size_t)r0 * OUTF + col) = o0;
            *reinterpret_cast<float2*>(out + (size_t)(r0 + 8) * OUTF + col) = o1;
        }
    }
}

// ---------------- launch -----------------------------------------------------
extern "C" void kernel_launch(void* const* d_in, const int* in_sizes, int n_in,
                              void* d_out, int out_size)
{
    (void)in_sizes; (void)n_in; (void)out_size;
    const float* x        = (const float*)d_in[0];
    const float* ln_gamma = (const float*)d_in[1];
    const float* ln_beta  = (const float*)d_in[2];
    const float* spline_w = (const float*)d_in[3];
    const float* base_w   = (const float*)d_in[4];
    const float* base_b   = (const float*)d_in[5];
    float* out = (float*)d_out;

    cudaFuncSetAttribute(gemm_kernel, cudaFuncAttributeMaxDynamicSharedMemorySize,
                         SMEM_BYTES);

    prep_kernel<<<OUTF + NROWS, 256>>>(spline_w, base_w, x, ln_gamma, ln_beta);
    gemm_kernel<<<dim3(8, 64), NTHR, SMEM_BYTES>>>(base_b, out);
}

// round 15
// speedup vs baseline: 1.2112x; 1.2112x over previous
#include <cuda_runtime.h>
#include <cuda_fp16.h>
#include <cstdint>
#include <cstddef>

#define NROWS  8192
#define INF    1024
#define OUTF   1024
#define KDIM   9216
#define KSTEP  64
#define NIT    144          // KDIM / 64
#define STAGES 3
#define ROWB   144          // 128 data bytes + 16 pad
#define A_SZ   (128 * ROWB)         // 18432
#define B_SZ   (128 * ROWB)         // 18432
#define STAGE_SZ (A_SZ + B_SZ)      // 36864
#define BAR_OFF (STAGES * STAGE_SZ) // 110592
#define SMEM_BYTES (BAR_OFF + 64)   // 110656 (x2 CTAs = 221312)
#define NTHR   288                  // 8 compute warps + 1 DMA warp

// ---------------- scratch (device globals) ----------------------------------
__device__ __align__(1024) __half g_G[(size_t)NROWS * KDIM];
__device__ __align__(1024) __half g_W[(size_t)OUTF * KDIM];

// ---------------- helpers ----------------------------------------------------
static __device__ __forceinline__ uint32_t smem_u32(const void* p) {
    uint32_t a;
    asm("{ .reg .u64 t; cvta.to.shared.u64 t, %1; cvt.u32.u64 %0, t; }"
        : "=r"(a) : "l"(p));
    return a;
}
static __device__ __forceinline__ void cp16(uint32_t s, const void* g) {
    asm volatile("cp.async.cg.shared.global [%0], [%1], 16;" :: "r"(s), "l"(g));
}
static __device__ __forceinline__ void mbar_init(uint32_t m, uint32_t c) {
    asm volatile("mbarrier.init.shared.b64 [%0], %1;" :: "r"(m), "r"(c) : "memory");
}
static __device__ __forceinline__ void mbar_arrive(uint32_t m) {
    asm volatile("mbarrier.arrive.shared.b64 _, [%0];" :: "r"(m) : "memory");
}
static __device__ __forceinline__ void cpasync_mbar_arrive_noinc(uint32_t m) {
    asm volatile("cp.async.mbarrier.arrive.noinc.shared.b64 [%0];" :: "r"(m) : "memory");
}
static __device__ __forceinline__ void mbar_wait(uint32_t m, uint32_t ph) {
    asm volatile(
        "{\n\t.reg .pred P;\n"
        "LW_%=:\n\t"
        "mbarrier.try_wait.parity.shared.b64 P, [%0], %1;\n\t"
        "@P bra LD_%=;\n\t"
        "bra LW_%=;\n"
        "LD_%=:\n\t}"
        :: "r"(m), "r"(ph) : "memory");
}
#define LDSM4(r, adr) \
    asm volatile("ldmatrix.sync.aligned.m8n8.x4.shared.b16 {%0,%1,%2,%3}, [%4];" \
                 : "=r"((r)[0]), "=r"((r)[1]), "=r"((r)[2]), "=r"((r)[3]) \
                 : "r"(adr))
static __device__ __forceinline__ void mma16816(
    float* c, const uint32_t* a, uint32_t b0, uint32_t b1)
{
    asm volatile(
        "mma.sync.aligned.m16n8k16.row.col.f32.f16.f16.f32 "
        "{%0,%1,%2,%3}, {%4,%5,%6,%7}, {%8,%9}, {%0,%1,%2,%3};"
        : "+f"(c[0]), "+f"(c[1]), "+f"(c[2]), "+f"(c[3])
        : "r"(a[0]), "r"(a[1]), "r"(a[2]), "r"(a[3]), "r"(b0), "r"(b1));
}
static __device__ __forceinline__ uint32_t pack_h2(float a, float b) {
    __half2 t = __floats2half2_rn(a, b);
    return *reinterpret_cast<uint32_t*>(&t);
}

// ---------------- kernel 1: prep (W convert + features), merged --------------
__global__ void prep_kernel(const float* __restrict__ spline_w,
                            const float* __restrict__ base_w,
                            const float* __restrict__ x,
                            const float* __restrict__ gamma,
                            const float* __restrict__ beta)
{
    const int tid = threadIdx.x;            // 256 threads

    if (blockIdx.x < OUTF) {
        const int o = blockIdx.x;
        const size_t rb = (size_t)o * KDIM;
        for (int k = tid; k < KDIM; k += 256) {
            float v = (k < 8192) ? spline_w[(size_t)o * 8192 + k]
                                 : base_w[(size_t)o * 1024 + (k - 8192)];
            g_W[rb + k] = __float2half_rn(v);
        }
        return;
    }

    const int row = blockIdx.x - OUTF;
    const int lane = tid & 31, wid = tid >> 5;

    const float4 v = reinterpret_cast<const float4*>(x + (size_t)row * INF)[tid];
    float s  = v.x + v.y + v.z + v.w;
    float sq = v.x * v.x + v.y * v.y + v.z * v.z + v.w * v.w;
#pragma unroll
    for (int o = 16; o > 0; o >>= 1) {
        s  += __shfl_xor_sync(0xFFFFFFFFu, s,  o);
        sq += __shfl_xor_sync(0xFFFFFFFFu, sq, o);
    }
    __shared__ float rs[8], rq[8], s_mu, s_rstd;
    if (lane == 0) { rs[wid] = s; rq[wid] = sq; }
    __syncthreads();
    if (tid == 0) {
        float S = 0.f, Q = 0.f;
#pragma unroll
        for (int i = 0; i < 8; i++) { S += rs[i]; Q += rq[i]; }
        float mu = S * (1.0f / INF);
        float var = Q * (1.0f / INF) - mu * mu;
        s_mu = mu;
        s_rstd = rsqrtf(var + 1e-5f);
    }
    __syncthreads();
    const float mu = s_mu, rstd = s_rstd;

    __half* gh = g_G + (size_t)row * KDIM;
    const float xv4[4] = { v.x, v.y, v.z, v.w };

#pragma unroll
    for (int e = 0; e < 4; e++) {
        const int in = tid * 4 + e;
        const float xv = xv4[e];
        const float xn = (xv - mu) * rstd * gamma[in] + beta[in];
        const float t0 = (xn + 2.0f) * 1.75f;   // (xn - grid_g)/DENOM = t0 - g
        float b[8];
#pragma unroll
        for (int g = 0; g < 8; g++) {
            float d = t0 - (float)g;
            b[g] = __expf(-d * d);
        }
        uint4 H;
        H.x = pack_h2(b[0], b[1]); H.y = pack_h2(b[2], b[3]);
        H.z = pack_h2(b[4], b[5]); H.w = pack_h2(b[6], b[7]);
        *reinterpret_cast<uint4*>(gh + (size_t)in * 8) = H;

        float sl = xv / (1.0f + __expf(-xv));     // silu(x), original x
        gh[8192 + in] = __float2half_rn(sl);
    }
}

// ---------------- kernel 2: mma.sync GEMM  Y = G W^T + b ---------------------
// CTA 128x128, 8 compute warps (32x64) + 1 DMA producer warp, K-step 64,
// 3-stage mbarrier ring with cp.async.mbarrier.arrive, 2 CTAs / SM.
__global__ void __launch_bounds__(NTHR, 2)
gemm_kernel(const float* __restrict__ bias, float* __restrict__ out)
{
    extern __shared__ __align__(128) char smem[];
    const uint32_t sb = smem_u32(smem);
    const int tid  = threadIdx.x;
    const int lane = tid & 31;
    const int wid  = tid >> 5;
    const int n0 = blockIdx.x * 128;
    const int m0 = blockIdx.y * 128;

    const uint32_t fullb  = sb + BAR_OFF;        // full[s]  = fullb + 8*s
    const uint32_t emptyb = sb + BAR_OFF + 8u * STAGES;

    if (tid == 0) {
#pragma unroll
        for (int s = 0; s < STAGES; s++) {
            mbar_init(fullb + 8u * s, 32);   // 32 producer lanes (cp.async arrive)
            mbar_init(emptyb + 8u * s, 8);   // 8 compute warps (lane0)
        }
    }
    __syncthreads();    // barrier init visible

    if (wid == 8) {
        // ================= producer (DMA) warp =================
        const int r0 = lane >> 3;            // 0..3
        const int sgs = lane & 7;            // 0..7
        const __half* pgA = g_G + (size_t)(m0 + r0) * KDIM + sgs * 8;
        const __half* pgB = g_W + (size_t)(n0 + r0) * KDIM + sgs * 8;
        const uint32_t dsA = (uint32_t)(r0 * ROWB + sgs * 16);
        const uint32_t dsB = (uint32_t)(A_SZ + r0 * ROWB + sgs * 16);

        int sp = 0, fp = 0;
        for (int it = 0; it < NIT; it++) {
            if (fp >= 1) mbar_wait(emptyb + 8u * sp, (uint32_t)((fp - 1) & 1));
            const uint32_t st = sb + (uint32_t)(sp * STAGE_SZ);
            const uint32_t kcol = (uint32_t)it * KSTEP;
            {
                const __half* ga = pgA + kcol;
                uint32_t da = st + dsA;
#pragma unroll 8
                for (int j = 0; j < 32; j++) {
                    cp16(da, ga);
                    da += 4 * ROWB;
                    ga += (size_t)4 * KDIM;
                }
            }
            {
                const __half* gb = pgB + kcol;
                uint32_t db = st + dsB;
#pragma unroll 8
                for (int j = 0; j < 32; j++) {
                    cp16(db, gb);
                    db += 4 * ROWB;
                    gb += (size_t)4 * KDIM;
                }
            }
            cpasync_mbar_arrive_noinc(fullb + 8u * sp);   // signal when complete
            if (++sp == STAGES) { sp = 0; fp++; }
        }
        return;     // producer exits; no epilogue tile
    }

    // ================= compute warps =================
    const int warp_m = wid & 3;     // 4 x 32 rows
    const int warp_n = wid >> 2;    // 2 x 64 cols

    const uint32_t aLane = (uint32_t)((warp_m * 32 + ((lane >> 3) & 1) * 8 + (lane & 7)) * ROWB
                                      + (lane >> 4) * 16);
    const uint32_t bLane = (uint32_t)(A_SZ
                                      + (warp_n * 64 + ((lane >> 4) & 1) * 8 + (lane & 7)) * ROWB
                                      + ((lane >> 3) & 1) * 16);

    float acc[64];
#pragma unroll
    for (int i = 0; i < 64; i++) acc[i] = 0.0f;

    int sc = 0, pc = 0;     // consumer stage + phase parity
    for (int it = 0; it < NIT; it++) {
        mbar_wait(fullb + 8u * sc, (uint32_t)pc);

        const uint32_t st = sb + (uint32_t)(sc * STAGE_SZ);
#pragma unroll
        for (int kh = 0; kh < 4; kh++) {
            const uint32_t khoff = (uint32_t)(kh * 32);
            uint32_t a[2][4], b[4][4];
#pragma unroll
            for (int ms = 0; ms < 2; ms++)
                LDSM4(a[ms], st + aLane + (uint32_t)(ms * 16 * ROWB) + khoff);
#pragma unroll
            for (int p = 0; p < 4; p++)
                LDSM4(b[p], st + bLane + (uint32_t)(p * 16 * ROWB) + khoff);
#pragma unroll
            for (int ms = 0; ms < 2; ms++) {
#pragma unroll
                for (int p = 0; p < 4; p++) {
                    mma16816(acc + (ms * 8 + 2 * p) * 4,     a[ms], b[p][0], b[p][1]);
                    mma16816(acc + (ms * 8 + 2 * p + 1) * 4, a[ms], b[p][2], b[p][3]);
                }
            }
        }
        __syncwarp();
        if (lane == 0) mbar_arrive(emptyb + 8u * sc);

        if (++sc == STAGES) { sc = 0; pc ^= 1; }
    }

    // ---- epilogue: add bias, store fp32 ----
    const int rbase = m0 + warp_m * 32 + (lane >> 2);
    const int cbase = n0 + warp_n * 64 + (lane & 3) * 2;
#pragma unroll
    for (int ms = 0; ms < 2; ms++) {
#pragma unroll
        for (int ns = 0; ns < 8; ns++) {
            const float* c = acc + (ms * 8 + ns) * 4;
            const int col = cbase + ns * 8;
            const float2 bb = *reinterpret_cast<const float2*>(bias + col);
            const int r0 = rbase + ms * 16;
            float2 o0 = { c[0] + bb.x, c[1] + bb.y };
            float2 o1 = { c[2] + bb.x, c[3] + bb.y };
            *reinterpret_cast<float2*>(out + (size_t)r0 * OUTF + col) = o0;
            *reinterpret_cast<float2*>(out + (size_t)(r0 + 8) * OUTF + col) = o1;
        }
    }
}

// ---------------- launch -----------------------------------------------------
extern "C" void kernel_launch(void* const* d_in, const int* in_sizes, int n_in,
                              void* d_out, int out_size)
{
    (void)in_sizes; (void)n_in; (void)out_size;
    const float* x        = (const float*)d_in[0];
    const float* ln_gamma = (const float*)d_in[1];
    const float* ln_beta  = (const float*)d_in[2];
    const float* spline_w = (const float*)d_in[3];
    const float* base_w   = (const float*)d_in[4];
    const float* base_b   = (const float*)d_in[5];
    float* out = (float*)d_out;

    cudaFuncSetAttribute(gemm_kernel, cudaFuncAttributeMaxDynamicSharedMemorySize,
                         SMEM_BYTES);

    prep_kernel<<<OUTF + NROWS, 256>>>(spline_w, base_w, x, ln_gamma, ln_beta);
    gemm_kernel<<<dim3(8, 64), NTHR, SMEM_BYTES>>>(base_b, out);
}

// round 16
// speedup vs baseline: 1.2713x; 1.0496x over previous
#include <cuda_runtime.h>
#include <cuda_fp16.h>
#include <cstdint>
#include <cstddef>

#define NROWS  8192
#define INF    1024
#define OUTF   1024
#define KDIM   9216
#define KSTEP  64
#define NIT    144          // KDIM / 64
#define STAGES 4
#define ROWB   144          // 128 data bytes + 16 pad
#define A_SZ   (128 * ROWB)         // 18432
#define B_SZ   (256 * ROWB)         // 36864
#define STAGE_SZ (A_SZ + B_SZ)      // 55296
#define BAR_OFF (STAGES * STAGE_SZ) // 221184
#define SMEM_BYTES (BAR_OFF + 96)   // 221280 (1 CTA/SM)
#define NTHR   320                  // 8 compute warps + 2 DMA warps

// ---------------- scratch (device globals) ----------------------------------
__device__ __align__(1024) __half g_G[(size_t)NROWS * KDIM];
__device__ __align__(1024) __half g_W[(size_t)OUTF * KDIM];

// ---------------- helpers ----------------------------------------------------
static __device__ __forceinline__ uint32_t smem_u32(const void* p) {
    uint32_t a;
    asm("{ .reg .u64 t; cvta.to.shared.u64 t, %1; cvt.u32.u64 %0, t; }"
        : "=r"(a) : "l"(p));
    return a;
}
static __device__ __forceinline__ void cp16(uint32_t s, const void* g) {
    asm volatile("cp.async.cg.shared.global [%0], [%1], 16;" :: "r"(s), "l"(g));
}
static __device__ __forceinline__ void mbar_init(uint32_t m, uint32_t c) {
    asm volatile("mbarrier.init.shared.b64 [%0], %1;" :: "r"(m), "r"(c) : "memory");
}
static __device__ __forceinline__ void mbar_arrive(uint32_t m) {
    asm volatile("mbarrier.arrive.shared.b64 _, [%0];" :: "r"(m) : "memory");
}
static __device__ __forceinline__ void cpasync_mbar_arrive_noinc(uint32_t m) {
    asm volatile("cp.async.mbarrier.arrive.noinc.shared.b64 [%0];" :: "r"(m) : "memory");
}
static __device__ __forceinline__ void mbar_wait(uint32_t m, uint32_t ph) {
    asm volatile(
        "{\n\t.reg .pred P;\n"
        "LW_%=:\n\t"
        "mbarrier.try_wait.parity.shared.b64 P, [%0], %1;\n\t"
        "@P bra LD_%=;\n\t"
        "bra LW_%=;\n"
        "LD_%=:\n\t}"
        :: "r"(m), "r"(ph) : "memory");
}
#define LDSM4(r, adr) \
    asm volatile("ldmatrix.sync.aligned.m8n8.x4.shared.b16 {%0,%1,%2,%3}, [%4];" \
                 : "=r"((r)[0]), "=r"((r)[1]), "=r"((r)[2]), "=r"((r)[3]) \
                 : "r"(adr))
static __device__ __forceinline__ void mma16816(
    float* c, const uint32_t* a, uint32_t b0, uint32_t b1)
{
    asm volatile(
        "mma.sync.aligned.m16n8k16.row.col.f32.f16.f16.f32 "
        "{%0,%1,%2,%3}, {%4,%5,%6,%7}, {%8,%9}, {%0,%1,%2,%3};"
        : "+f"(c[0]), "+f"(c[1]), "+f"(c[2]), "+f"(c[3])
        : "r"(a[0]), "r"(a[1]), "r"(a[2]), "r"(a[3]), "r"(b0), "r"(b1));
}
static __device__ __forceinline__ uint32_t pack_h2(float a, float b) {
    __half2 t = __floats2half2_rn(a, b);
    return *reinterpret_cast<uint32_t*>(&t);
}

// ---------------- kernel 1: prep (W convert + features), merged --------------
__global__ void prep_kernel(const float* __restrict__ spline_w,
                            const float* __restrict__ base_w,
                            const float* __restrict__ x,
                            const float* __restrict__ gamma,
                            const float* __restrict__ beta)
{
    const int tid = threadIdx.x;            // 256 threads

    if (blockIdx.x < OUTF) {
        // ---- W row: convert [spline_w | base_w] -> fp16 (vectorized) ----
        const int o = blockIdx.x;
        const size_t rb = (size_t)o * KDIM;
        for (int k = tid * 4; k < KDIM; k += 1024) {
            float4 v;
            if (k < 8192) v = *reinterpret_cast<const float4*>(spline_w + (size_t)o * 8192 + k);
            else          v = *reinterpret_cast<const float4*>(base_w + (size_t)o * 1024 + (k - 8192));
            uint2 h;
            h.x = pack_h2(v.x, v.y);
            h.y = pack_h2(v.z, v.w);
            *reinterpret_cast<uint2*>(&g_W[rb + k]) = h;
        }
        return;
    }

    const int row = blockIdx.x - OUTF;
    const int lane = tid & 31, wid = tid >> 5;

    const float4 v = reinterpret_cast<const float4*>(x + (size_t)row * INF)[tid];
    float s  = v.x + v.y + v.z + v.w;
    float sq = v.x * v.x + v.y * v.y + v.z * v.z + v.w * v.w;
#pragma unroll
    for (int o = 16; o > 0; o >>= 1) {
        s  += __shfl_xor_sync(0xFFFFFFFFu, s,  o);
        sq += __shfl_xor_sync(0xFFFFFFFFu, sq, o);
    }
    __shared__ float rs[8], rq[8], s_mu, s_rstd;
    if (lane == 0) { rs[wid] = s; rq[wid] = sq; }
    __syncthreads();
    if (tid == 0) {
        float S = 0.f, Q = 0.f;
#pragma unroll
        for (int i = 0; i < 8; i++) { S += rs[i]; Q += rq[i]; }
        float mu = S * (1.0f / INF);
        float var = Q * (1.0f / INF) - mu * mu;
        s_mu = mu;
        s_rstd = rsqrtf(var + 1e-5f);
    }
    __syncthreads();
    const float mu = s_mu, rstd = s_rstd;

    __half* gh = g_G + (size_t)row * KDIM;
    const float xv4[4] = { v.x, v.y, v.z, v.w };

#pragma unroll
    for (int e = 0; e < 4; e++) {
        const int in = tid * 4 + e;
        const float xv = xv4[e];
        const float xn = (xv - mu) * rstd * gamma[in] + beta[in];
        const float t0 = (xn + 2.0f) * 1.75f;   // (xn - grid_g)/DENOM = t0 - g
        float b[8];
#pragma unroll
        for (int g = 0; g < 8; g++) {
            float d = t0 - (float)g;
            b[g] = __expf(-d * d);
        }
        uint4 H;
        H.x = pack_h2(b[0], b[1]); H.y = pack_h2(b[2], b[3]);
        H.z = pack_h2(b[4], b[5]); H.w = pack_h2(b[6], b[7]);
        *reinterpret_cast<uint4*>(gh + (size_t)in * 8) = H;

        float sl = xv / (1.0f + __expf(-xv));     // silu(x), original x
        gh[8192 + in] = __float2half_rn(sl);
    }
}

// ---------------- kernel 2: mma.sync GEMM  Y = G W^T + b ---------------------
// CTA 128x256, 8 compute warps of 64x64 (2m x 4n) + 2 DMA warps, K-step 64,
// 4-stage mbarrier ring with cp.async.mbarrier.arrive, 1 CTA / SM.
__global__ void __launch_bounds__(NTHR, 1)
gemm_kernel(const float* __restrict__ bias, float* __restrict__ out)
{
    extern __shared__ __align__(128) char smem[];
    const uint32_t sb = smem_u32(smem);
    const int tid  = threadIdx.x;
    const int lane = tid & 31;
    const int wid  = tid >> 5;
    const int n0 = blockIdx.x * 256;
    const int m0 = blockIdx.y * 128;

    const uint32_t fullb  = sb + BAR_OFF;        // full[s]  = fullb + 8*s
    const uint32_t emptyb = sb + BAR_OFF + 8u * STAGES;

    if (tid == 0) {
#pragma unroll
        for (int s = 0; s < STAGES; s++) {
            mbar_init(fullb + 8u * s, 64);   // 64 producer lanes (cp.async arrive)
            mbar_init(emptyb + 8u * s, 8);   // 8 compute warps (lane0)
        }
    }
    __syncthreads();    // barrier init visible

    if (wid >= 8) {
        // ================= producer (DMA) warps =================
        const int d = wid - 8;               // 0,1
        const int r0 = lane >> 3;            // 0..3
        const int sgs = lane & 7;            // 0..7
        // warp d: A rows [d*64, d*64+64), B rows [d*128, d*128+128)
        const __half* pgA = g_G + (size_t)(m0 + d * 64 + r0) * KDIM + sgs * 8;
        const __half* pgB = g_W + (size_t)(n0 + d * 128 + r0) * KDIM + sgs * 8;
        const uint32_t dsA = (uint32_t)((d * 64 + r0) * ROWB + sgs * 16);
        const uint32_t dsB = (uint32_t)(A_SZ + (d * 128 + r0) * ROWB + sgs * 16);

        int sp = 0, fp = 0;
        for (int it = 0; it < NIT; it++) {
            if (fp >= 1) mbar_wait(emptyb + 8u * sp, (uint32_t)((fp - 1) & 1));
            const uint32_t st = sb + (uint32_t)(sp * STAGE_SZ);
            const uint32_t kcol = (uint32_t)it * KSTEP;
            {
                const __half* ga = pgA + kcol;
                uint32_t da = st + dsA;
#pragma unroll 8
                for (int j = 0; j < 16; j++) {          // 64 A rows
                    cp16(da, ga);
                    da += 4 * ROWB;
                    ga += (size_t)4 * KDIM;
                }
            }
            {
                const __half* gb = pgB + kcol;
                uint32_t db = st + dsB;
#pragma unroll 8
                for (int j = 0; j < 32; j++) {          // 128 B rows
                    cp16(db, gb);
                    db += 4 * ROWB;
                    gb += (size_t)4 * KDIM;
                }
            }
            cpasync_mbar_arrive_noinc(fullb + 8u * sp);   // signal on completion
            if (++sp == STAGES) { sp = 0; fp++; }
        }
        return;     // producers exit; no epilogue tile
    }

    // ================= compute warps =================
    const int warp_m = wid & 1;     // 2 x 64 rows
    const int warp_n = wid >> 1;    // 4 x 64 cols

    const uint32_t aLane = (uint32_t)((warp_m * 64 + ((lane >> 3) & 1) * 8 + (lane & 7)) * ROWB
                                      + (lane >> 4) * 16);
    const uint32_t bLane = (uint32_t)(A_SZ
                                      + (warp_n * 64 + ((lane >> 4) & 1) * 8 + (lane & 7)) * ROWB
                                      + ((lane >> 3) & 1) * 16);

    float acc[128];
#pragma unroll
    for (int i = 0; i < 128; i++) acc[i] = 0.0f;

    int sc = 0, pc = 0;     // consumer stage + phase parity
    for (int it = 0; it < NIT; it++) {
        mbar_wait(fullb + 8u * sc, (uint32_t)pc);

        const uint32_t st = sb + (uint32_t)(sc * STAGE_SZ);
#pragma unroll
        for (int kh = 0; kh < 4; kh++) {
            const uint32_t khoff = (uint32_t)(kh * 32);
            uint32_t a[4][4], b[4][4];
#pragma unroll
            for (int ms = 0; ms < 4; ms++)
                LDSM4(a[ms], st + aLane + (uint32_t)(ms * 16 * ROWB) + khoff);
#pragma unroll
            for (int p = 0; p < 4; p++)
                LDSM4(b[p], st + bLane + (uint32_t)(p * 16 * ROWB) + khoff);
#pragma unroll
            for (int ms = 0; ms < 4; ms++) {
#pragma unroll
                for (int p = 0; p < 4; p++) {
                    mma16816(acc + (ms * 8 + 2 * p) * 4,     a[ms], b[p][0], b[p][1]);
                    mma16816(acc + (ms * 8 + 2 * p + 1) * 4, a[ms], b[p][2], b[p][3]);
                }
            }
        }
        __syncwarp();
        if (lane == 0) mbar_arrive(emptyb + 8u * sc);

        if (++sc == STAGES) { sc = 0; pc ^= 1; }
    }

    // ---- epilogue: add bias, store fp32 ----
    const int rbase = m0 + warp_m * 64 + (lane >> 2);
    const int cbase = n0 + warp_n * 64 + (lane & 3) * 2;
#pragma unroll
    for (int ms = 0; ms < 4; ms++) {
#pragma unroll
        for (int ns = 0; ns < 8; ns++) {
            const float* c = acc + (ms * 8 + ns) * 4;
            const int col = cbase + ns * 8;
            const float2 bb = *reinterpret_cast<const float2*>(bias + col);
            const int r0 = rbase + ms * 16;
            float2 o0 = { c[0] + bb.x, c[1] + bb.y };
            float2 o1 = { c[2] + bb.x, c[3] + bb.y };
            *reinterpret_cast<float2*>(out + (size_t)r0 * OUTF + col) = o0;
            *reinterpret_cast<float2*>(out + (size_t)(r0 + 8) * OUTF + col) = o1;
        }
    }
}

// ---------------- launch -----------------------------------------------------
extern "C" void kernel_launch(void* const* d_in, const int* in_sizes, int n_in,
                              void* d_out, int out_size)
{
    (void)in_sizes; (void)n_in; (void)out_size;
    const float* x        = (const float*)d_in[0];
    const float* ln_gamma = (const float*)d_in[1];
    const float* ln_beta  = (const float*)d_in[2];
    const float* spline_w = (const float*)d_in[3];
    const float* base_w   = (const float*)d_in[4];
    const float* base_b   = (const float*)d_in[5];
    float* out = (float*)d_out;

    cudaFuncSetAttribute(gemm_kernel, cudaFuncAttributeMaxDynamicSharedMemorySize,
                         SMEM_BYTES);

    prep_kernel<<<OUTF + NROWS, 256>>>(spline_w, base_w, x, ln_gamma, ln_beta);
    gemm_kernel<<<dim3(4, 64), NTHR, SMEM_BYTES>>>(base_b, out);
}

// round 17
// speedup vs baseline: 1.3224x; 1.0402x over previous
#include <cuda_runtime.h>
#include <cuda_fp16.h>
#include <cstdint>
#include <cstddef>

#define NROWS  8192
#define INF    1024
#define OUTF   1024
#define KDIM   9216
#define KSTEP  64
#define NIT    144          // KDIM / 64
#define STAGES 4
#define ROWB   144          // 128 data bytes + 16 pad
#define A_SZ   (128 * ROWB)         // 18432
#define B_SZ   (256 * ROWB)         // 36864
#define STAGE_SZ (A_SZ + B_SZ)      // 55296
#define BAR_OFF (STAGES * STAGE_SZ) // 221184
#define SMEM_BYTES (BAR_OFF + 96)   // 221280 (1 CTA/SM)
#define NTHR   320                  // 8 compute warps + 2 DMA warps

// ---------------- scratch (device globals) ----------------------------------
__device__ __align__(1024) __half g_G[(size_t)NROWS * KDIM];
__device__ __align__(1024) __half g_W[(size_t)OUTF * KDIM];

// ---------------- helpers ----------------------------------------------------
static __device__ __forceinline__ uint32_t smem_u32(const void* p) {
    uint32_t a;
    asm("{ .reg .u64 t; cvta.to.shared.u64 t, %1; cvt.u32.u64 %0, t; }"
        : "=r"(a) : "l"(p));
    return a;
}
static __device__ __forceinline__ void cp16(uint32_t s, const void* g) {
    asm volatile("cp.async.cg.shared.global [%0], [%1], 16;" :: "r"(s), "l"(g));
}
static __device__ __forceinline__ void mbar_init(uint32_t m, uint32_t c) {
    asm volatile("mbarrier.init.shared.b64 [%0], %1;" :: "r"(m), "r"(c) : "memory");
}
static __device__ __forceinline__ void mbar_arrive(uint32_t m) {
    asm volatile("mbarrier.arrive.shared.b64 _, [%0];" :: "r"(m) : "memory");
}
static __device__ __forceinline__ void cpasync_mbar_arrive_noinc(uint32_t m) {
    asm volatile("cp.async.mbarrier.arrive.noinc.shared.b64 [%0];" :: "r"(m) : "memory");
}
static __device__ __forceinline__ void mbar_wait(uint32_t m, uint32_t ph) {
    asm volatile(
        "{\n\t.reg .pred P;\n"
        "LW_%=:\n\t"
        "mbarrier.try_wait.parity.shared.b64 P, [%0], %1;\n\t"
        "@P bra LD_%=;\n\t"
        "bra LW_%=;\n"
        "LD_%=:\n\t}"
        :: "r"(m), "r"(ph) : "memory");
}
#define LDSM4(r, adr) \
    asm volatile("ldmatrix.sync.aligned.m8n8.x4.shared.b16 {%0,%1,%2,%3}, [%4];" \
                 : "=r"((r)[0]), "=r"((r)[1]), "=r"((r)[2]), "=r"((r)[3]) \
                 : "r"(adr))
static __device__ __forceinline__ void mma16816(
    float* c, const uint32_t* a, uint32_t b0, uint32_t b1)
{
    asm volatile(
        "mma.sync.aligned.m16n8k16.row.col.f32.f16.f16.f32 "
        "{%0,%1,%2,%3}, {%4,%5,%6,%7}, {%8,%9}, {%0,%1,%2,%3};"
        : "+f"(c[0]), "+f"(c[1]), "+f"(c[2]), "+f"(c[3])
        : "r"(a[0]), "r"(a[1]), "r"(a[2]), "r"(a[3]), "r"(b0), "r"(b1));
}
static __device__ __forceinline__ uint32_t pack_h2(float a, float b) {
    __half2 t = __floats2half2_rn(a, b);
    return *reinterpret_cast<uint32_t*>(&t);
}

// ---------------- kernel 1: prep (W convert + features), merged --------------
__global__ void prep_kernel(const float* __restrict__ spline_w,
                            const float* __restrict__ base_w,
                            const float* __restrict__ x,
                            const float* __restrict__ gamma,
                            const float* __restrict__ beta)
{
    const int tid = threadIdx.x;            // 256 threads

    if (blockIdx.x < OUTF) {
        // ---- W row: convert [spline_w | base_w] -> fp16 (vectorized) ----
        const int o = blockIdx.x;
        const size_t rb = (size_t)o * KDIM;
        for (int k = tid * 4; k < KDIM; k += 1024) {
            float4 v;
            if (k < 8192) v = *reinterpret_cast<const float4*>(spline_w + (size_t)o * 8192 + k);
            else          v = *reinterpret_cast<const float4*>(base_w + (size_t)o * 1024 + (k - 8192));
            uint2 h;
            h.x = pack_h2(v.x, v.y);
            h.y = pack_h2(v.z, v.w);
            *reinterpret_cast<uint2*>(&g_W[rb + k]) = h;
        }
        return;
    }

    const int row = blockIdx.x - OUTF;
    const int lane = tid & 31, wid = tid >> 5;

    const float4 v = reinterpret_cast<const float4*>(x + (size_t)row * INF)[tid];
    float s  = v.x + v.y + v.z + v.w;
    float sq = v.x * v.x + v.y * v.y + v.z * v.z + v.w * v.w;
#pragma unroll
    for (int o = 16; o > 0; o >>= 1) {
        s  += __shfl_xor_sync(0xFFFFFFFFu, s,  o);
        sq += __shfl_xor_sync(0xFFFFFFFFu, sq, o);
    }
    __shared__ float rs[8], rq[8], s_mu, s_rstd;
    if (lane == 0) { rs[wid] = s; rq[wid] = sq; }
    __syncthreads();
    if (tid == 0) {
        float S = 0.f, Q = 0.f;
#pragma unroll
        for (int i = 0; i < 8; i++) { S += rs[i]; Q += rq[i]; }
        float mu = S * (1.0f / INF);
        float var = Q * (1.0f / INF) - mu * mu;
        s_mu = mu;
        s_rstd = rsqrtf(var + 1e-5f);
    }
    __syncthreads();
    const float mu = s_mu, rstd = s_rstd;

    __half* gh = g_G + (size_t)row * KDIM;
    const float xv4[4] = { v.x, v.y, v.z, v.w };
    uint32_t silp[2];
    __half sil4[4];

#pragma unroll
    for (int e = 0; e < 4; e++) {
        const int in = tid * 4 + e;
        const float xv = xv4[e];
        const float xn = (xv - mu) * rstd * gamma[in] + beta[in];
        const float t0 = (xn + 2.0f) * 1.75f;   // (xn - grid_g)/DENOM = t0 - g
        float b[8];
#pragma unroll
        for (int g = 0; g < 8; g++) {
            float d = t0 - (float)g;
            b[g] = __expf(-d * d);
        }
        uint4 H;
        H.x = pack_h2(b[0], b[1]); H.y = pack_h2(b[2], b[3]);
        H.z = pack_h2(b[4], b[5]); H.w = pack_h2(b[6], b[7]);
        *reinterpret_cast<uint4*>(gh + (size_t)in * 8) = H;

        float sl = xv / (1.0f + __expf(-xv));     // silu(x), original x
        sil4[e] = __float2half_rn(sl);
    }
    silp[0] = pack_h2(__half2float(sil4[0]), __half2float(sil4[1]));
    silp[1] = pack_h2(__half2float(sil4[2]), __half2float(sil4[3]));
    *reinterpret_cast<uint2*>(gh + 8192 + tid * 4) = *reinterpret_cast<uint2*>(silp);
}

// ---------------- kernel 2: mma.sync GEMM  Y = G W^T + b ---------------------
// CTA 128x256, 8 compute warps of 64x64 (2m x 4n) + 2 DMA warps, K-step 64,
// 4-stage mbarrier ring with cp.async.mbarrier.arrive, fragment
// double-buffering across kh, 1 CTA / SM.
#define LDF(buf, kh) do { \
    const uint32_t khoff_ = (uint32_t)((kh) * 32); \
    _Pragma("unroll") \
    for (int ms = 0; ms < 4; ms++) \
        LDSM4(a[buf][ms], st + aLane + (uint32_t)(ms * 16 * ROWB) + khoff_); \
    _Pragma("unroll") \
    for (int p = 0; p < 4; p++) \
        LDSM4(b[buf][p], st + bLane + (uint32_t)(p * 16 * ROWB) + khoff_); \
} while (0)

#define DOM(buf) do { \
    _Pragma("unroll") \
    for (int ms = 0; ms < 4; ms++) { \
        _Pragma("unroll") \
        for (int p = 0; p < 4; p++) { \
            mma16816(acc + (ms * 8 + 2 * p) * 4,     a[buf][ms], b[buf][p][0], b[buf][p][1]); \
            mma16816(acc + (ms * 8 + 2 * p + 1) * 4, a[buf][ms], b[buf][p][2], b[buf][p][3]); \
        } \
    } \
} while (0)

__global__ void __launch_bounds__(NTHR, 1)
gemm_kernel(const float* __restrict__ bias, float* __restrict__ out)
{
    extern __shared__ __align__(128) char smem[];
    const uint32_t sb = smem_u32(smem);
    const int tid  = threadIdx.x;
    const int lane = tid & 31;
    const int wid  = tid >> 5;
    const int n0 = blockIdx.x * 256;
    const int m0 = blockIdx.y * 128;

    const uint32_t fullb  = sb + BAR_OFF;        // full[s]  = fullb + 8*s
    const uint32_t emptyb = sb + BAR_OFF + 8u * STAGES;

    if (tid == 0) {
#pragma unroll
        for (int s = 0; s < STAGES; s++) {
            mbar_init(fullb + 8u * s, 64);   // 64 producer lanes (cp.async arrive)
            mbar_init(emptyb + 8u * s, 8);   // 8 compute warps (lane0)
        }
    }
    __syncthreads();    // barrier init visible

    if (wid >= 8) {
        // ================= producer (DMA) warps =================
        const int d = wid - 8;               // 0,1
        const int r0 = lane >> 3;            // 0..3
        const int sgs = lane & 7;            // 0..7
        const __half* pgA = g_G + (size_t)(m0 + d * 64 + r0) * KDIM + sgs * 8;
        const __half* pgB = g_W + (size_t)(n0 + d * 128 + r0) * KDIM + sgs * 8;
        const uint32_t dsA = (uint32_t)((d * 64 + r0) * ROWB + sgs * 16);
        const uint32_t dsB = (uint32_t)(A_SZ + (d * 128 + r0) * ROWB + sgs * 16);

        int sp = 0, fp = 0;
        for (int it = 0; it < NIT; it++) {
            if (fp >= 1) mbar_wait(emptyb + 8u * sp, (uint32_t)((fp - 1) & 1));
            const uint32_t st = sb + (uint32_t)(sp * STAGE_SZ);
            const uint32_t kcol = (uint32_t)it * KSTEP;
            {
                const __half* ga = pgA + kcol;
                uint32_t da = st + dsA;
#pragma unroll 8
                for (int j = 0; j < 16; j++) {          // 64 A rows
                    cp16(da, ga);
                    da += 4 * ROWB;
                    ga += (size_t)4 * KDIM;
                }
            }
            {
                const __half* gb = pgB + kcol;
                uint32_t db = st + dsB;
#pragma unroll 8
                for (int j = 0; j < 32; j++) {          // 128 B rows
                    cp16(db, gb);
                    db += 4 * ROWB;
                    gb += (size_t)4 * KDIM;
                }
            }
            cpasync_mbar_arrive_noinc(fullb + 8u * sp);   // signal on completion
            if (++sp == STAGES) { sp = 0; fp++; }
        }
        return;     // producers exit; no epilogue tile
    }

    // ================= compute warps =================
    const int warp_m = wid & 1;     // 2 x 64 rows
    const int warp_n = wid >> 1;    // 4 x 64 cols

    const uint32_t aLane = (uint32_t)((warp_m * 64 + ((lane >> 3) & 1) * 8 + (lane & 7)) * ROWB
                                      + (lane >> 4) * 16);
    const uint32_t bLane = (uint32_t)(A_SZ
                                      + (warp_n * 64 + ((lane >> 4) & 1) * 8 + (lane & 7)) * ROWB
                                      + ((lane >> 3) & 1) * 16);

    float acc[128];
#pragma unroll
    for (int i = 0; i < 128; i++) acc[i] = 0.0f;

    int sc = 0, pc = 0;     // consumer stage + phase parity
    for (int it = 0; it < NIT; it++) {
        mbar_wait(fullb + 8u * sc, (uint32_t)pc);

        const uint32_t st = sb + (uint32_t)(sc * STAGE_SZ);
        uint32_t a[2][4][4], b[2][4][4];
        LDF(0, 0);
        LDF(1, 1);
        DOM(0);             // kh = 0
        LDF(0, 2);
        DOM(1);             // kh = 1
        LDF(1, 3);
        DOM(0);             // kh = 2
        DOM(1);             // kh = 3

        __syncwarp();
        if (lane == 0) mbar_arrive(emptyb + 8u * sc);

        if (++sc == STAGES) { sc = 0; pc ^= 1; }
    }

    // ---- epilogue: add bias, store fp32 ----
    const int rbase = m0 + warp_m * 64 + (lane >> 2);
    const int cbase = n0 + warp_n * 64 + (lane & 3) * 2;
#pragma unroll
    for (int ms = 0; ms < 4; ms++) {
#pragma unroll
        for (int ns = 0; ns < 8; ns++) {
            const float* c = acc + (ms * 8 + ns) * 4;
            const int col = cbase + ns * 8;
            const float2 bb = *reinterpret_cast<const float2*>(bias + col);
            const int r0 = rbase + ms * 16;
            float2 o0 = { c[0] + bb.x, c[1] + bb.y };
            float2 o1 = { c[2] + bb.x, c[3] + bb.y };
            *reinterpret_cast<float2*>(out + (size_t)r0 * OUTF + col) = o0;
            *reinterpret_cast<float2*>(out + (size_t)(r0 + 8) * OUTF + col) = o1;
        }
    }
}

// ---------------- launch -----------------------------------------------------
extern "C" void kernel_launch(void* const* d_in, const int* in_sizes, int n_in,
                              void* d_out, int out_size)
{
    (void)in_sizes; (void)n_in; (void)out_size;
    const float* x        = (const float*)d_in[0];
    const float* ln_gamma = (const float*)d_in[1];
    const float* ln_beta  = (const float*)d_in[2];
    const float* spline_w = (const float*)d_in[3];
    const float* base_w   = (const float*)d_in[4];
    const float* base_b   = (const float*)d_in[5];
    float* out = (float*)d_out;

    cudaFuncSetAttribute(gemm_kernel, cudaFuncAttributeMaxDynamicSharedMemorySize,
                         SMEM_BYTES);

    prep_kernel<<<OUTF + NROWS, 256>>>(spline_w, base_w, x, ln_gamma, ln_beta);
    gemm_kernel<<<dim3(4, 64), NTHR, SMEM_BYTES>>>(base_b, out);
}